// round 2
// baseline (speedup 1.0000x reference)
#include <cuda_runtime.h>

// Problem constants
#define B_   1024
#define T_   512
#define I_   16
#define H_   50
#define G_   200     // 4*H
#define FCD  64
#define NB   4       // batch rows per block
#define NTH  448     // 14 warps: warps 0-6 = group A, warps 7-13 = group B
#define HCH  13      // h chunks: 52 padded floats / 4

// Layer-1 hidden sequence scratch: [B][T][H] floats = 104.9 MB
__device__ float g_h1[B_ * T_ * H_];

typedef unsigned long long ull;

// ---- f32x2 packed helpers (sm_103a FFMA2) ----
__device__ __forceinline__ void fma2(ull& acc, ull a, ull b) {
    asm("fma.rn.f32x2 %0, %1, %2, %0;" : "+l"(acc) : "l"(a), "l"(b));
}
__device__ __forceinline__ ull pk2(float x, float y) {
    ull r;
    asm("mov.b64 %0, {%1, %2};" : "=l"(r) : "f"(x), "f"(y));
    return r;
}
__device__ __forceinline__ float2 unpk(ull v) {
    float2 r;
    asm("mov.b64 {%0, %1}, %2;" : "=f"(r.x), "=f"(r.y) : "l"(v));
    return r;
}

__device__ __forceinline__ float sigf(float x) {
    return 1.0f / (1.0f + __expf(-x));
}
__device__ __forceinline__ float tanh_f(float x) {
    return 2.0f / (1.0f + __expf(-2.0f * x)) - 1.0f;
}

// One LSTM layer, persistent per-block over all T timesteps.
// IN    = logical input width (16 layer1, 50 layer2)
// INPAD = padded input width, multiple of 4 (20 / 52)
// Group A (tid<224): x-part (+bias, + first AH h-chunks). Group B: rest of h-part.
template <int IN, int INPAD, bool FINAL>
__global__ __launch_bounds__(NTH, 2)
void lstm_kernel(const float* __restrict__ in,
                 const float* __restrict__ w_ih,   // [G, IN]
                 const float* __restrict__ w_hh,   // [G, H]
                 const float* __restrict__ b_ih,   // [G]
                 const float* __restrict__ b_hh,   // [G]
                 const float* __restrict__ fc1_w,  // [FCD, H]
                 const float* __restrict__ fc1_b,  // [FCD]
                 const float* __restrict__ fc2_w,  // [1, FCD]
                 const float* __restrict__ fc2_b,  // [1]
                 float* __restrict__ out)          // [B, 1]
{
    constexpr int XCH = INPAD / 4;        // x chunks
    constexpr int TCH = XCH + HCH;        // total chunks (even for both layers)
    constexpr int MCH = TCH / 2;          // chunks per group (9 / 13)
    constexpr int AH  = MCH - XCH;        // h-chunks owned by group A (4 / 0)
    constexpr int PF  = 48;               // prefetch lanes
    constexpr int UNR = (NB * IN + PF - 1) / PF;

    __shared__ __align__(16) float h_sh[NB][52];        // hidden state (padded)
    __shared__ __align__(16) float x_sh[2][NB][INPAD];  // double-buffered input tile
    __shared__ ull  gp[2][NB][G_];                      // packed gate partials per group
    __shared__ float fcsh[FCD];

    const int tid  = threadIdx.x;
    const int row0 = blockIdx.x * NB;
    const bool grpA = (tid < 224);
    const int  g    = grpA ? tid : tid - 224;   // gate index if < 200
    const bool isGate = (g < G_);
    const bool isPf   = !isGate;                // 48 boundary lanes do prefetch
    const int  pid    = grpA ? (tid - 200) : (tid - 400);  // [0,48)

    const float* input = FINAL ? (const float*)g_h1 : in;
    const int in_stride = T_ * IN;

    // ---- zero shared state (pads must be 0: pad*w could be NaN otherwise) ----
    for (int i = tid; i < NB * 52; i += NTH) ((float*)h_sh)[i] = 0.0f;
    for (int i = tid; i < 2 * NB * INPAD; i += NTH) ((float*)x_sh)[i] = 0.0f;
    __syncthreads();

    // ---- load this thread's weight chunks into registers (f32x2 packed) ----
    ull w2[MCH][2];
    float bias = 0.0f;
    if (isGate) {
        if (grpA) {
            #pragma unroll
            for (int c = 0; c < XCH; c++) {
                float a0 = (4*c+0 < IN) ? __ldg(&w_ih[g*IN + 4*c+0]) : 0.0f;
                float a1 = (4*c+1 < IN) ? __ldg(&w_ih[g*IN + 4*c+1]) : 0.0f;
                float a2 = (4*c+2 < IN) ? __ldg(&w_ih[g*IN + 4*c+2]) : 0.0f;
                float a3 = (4*c+3 < IN) ? __ldg(&w_ih[g*IN + 4*c+3]) : 0.0f;
                w2[c][0] = pk2(a0, a1);
                w2[c][1] = pk2(a2, a3);
            }
            #pragma unroll
            for (int ch = 0; ch < AH; ch++) {
                float a0 = (4*ch+0 < H_) ? __ldg(&w_hh[g*H_ + 4*ch+0]) : 0.0f;
                float a1 = (4*ch+1 < H_) ? __ldg(&w_hh[g*H_ + 4*ch+1]) : 0.0f;
                float a2 = (4*ch+2 < H_) ? __ldg(&w_hh[g*H_ + 4*ch+2]) : 0.0f;
                float a3 = (4*ch+3 < H_) ? __ldg(&w_hh[g*H_ + 4*ch+3]) : 0.0f;
                w2[XCH + ch][0] = pk2(a0, a1);
                w2[XCH + ch][1] = pk2(a2, a3);
            }
            bias = __ldg(&b_ih[g]) + __ldg(&b_hh[g]);
        } else {
            #pragma unroll
            for (int ch = AH; ch < HCH; ch++) {
                float a0 = (4*ch+0 < H_) ? __ldg(&w_hh[g*H_ + 4*ch+0]) : 0.0f;
                float a1 = (4*ch+1 < H_) ? __ldg(&w_hh[g*H_ + 4*ch+1]) : 0.0f;
                float a2 = (4*ch+2 < H_) ? __ldg(&w_hh[g*H_ + 4*ch+2]) : 0.0f;
                float a3 = (4*ch+3 < H_) ? __ldg(&w_hh[g*H_ + 4*ch+3]) : 0.0f;
                w2[ch - AH][0] = pk2(a0, a1);
                w2[ch - AH][1] = pk2(a2, a3);
            }
        }
    }

    // ---- t = 0 input tile (cooperative) ----
    for (int e = tid; e < NB * IN; e += NTH) {
        int r = e / IN, k = e - r * IN;
        x_sh[0][r][k] = input[(row0 + r) * in_stride + k];
    }
    __syncthreads();

    // combine mapping: thread tid<200 owns cell (rc, jc)
    const int rc = tid / H_;
    const int jc = tid - rc * H_;
    float c_state = 0.0f;

    int buf = 0;
    for (int t = 0; t < T_; t++) {
        // -- region 1: prefetch lanes batch-issue next-step global loads (MLP) --
        float pv[UNR];
        if (isPf && t + 1 < T_) {
            #pragma unroll
            for (int i = 0; i < UNR; i++) {
                int e = pid + i * PF;
                if (e < NB * IN) {
                    int r = e / IN, k = e - r * IN;
                    pv[i] = input[(row0 + r) * in_stride + (t + 1) * IN + k];
                }
            }
        }

        // -- region 2: gate partials --
        if (isGate) {
            ull acc[NB];
            #pragma unroll
            for (int r = 0; r < NB; r++) acc[r] = pk2(grpA ? bias : 0.0f, 0.0f);

            if (grpA) {
                #pragma unroll
                for (int c = 0; c < XCH; c++) {
                    #pragma unroll
                    for (int r = 0; r < NB; r++) {
                        const ulonglong2 v = *(const ulonglong2*)&x_sh[buf][r][4 * c];
                        fma2(acc[r], w2[c][0], v.x);
                        fma2(acc[r], w2[c][1], v.y);
                    }
                }
                #pragma unroll
                for (int ch = 0; ch < AH; ch++) {
                    #pragma unroll
                    for (int r = 0; r < NB; r++) {
                        const ulonglong2 v = *(const ulonglong2*)&h_sh[r][4 * ch];
                        fma2(acc[r], w2[XCH + ch][0], v.x);
                        fma2(acc[r], w2[XCH + ch][1], v.y);
                    }
                }
                #pragma unroll
                for (int r = 0; r < NB; r++) gp[0][r][g] = acc[r];
            } else {
                #pragma unroll
                for (int ch = AH; ch < HCH; ch++) {
                    #pragma unroll
                    for (int r = 0; r < NB; r++) {
                        const ulonglong2 v = *(const ulonglong2*)&h_sh[r][4 * ch];
                        fma2(acc[r], w2[ch - AH][0], v.x);
                        fma2(acc[r], w2[ch - AH][1], v.y);
                    }
                }
                #pragma unroll
                for (int r = 0; r < NB; r++) gp[1][r][g] = acc[r];
            }
        }

        // -- region 3: commit prefetched inputs into the other buffer --
        if (isPf && t + 1 < T_) {
            #pragma unroll
            for (int i = 0; i < UNR; i++) {
                int e = pid + i * PF;
                if (e < NB * IN) {
                    int r = e / IN, k = e - r * IN;
                    x_sh[buf ^ 1][r][k] = pv[i];
                }
            }
        }
        __syncthreads();

        // -- combine: LSTM cell update (gate order i, f, g, o) --
        if (tid < G_) {
            float2 a0 = unpk(gp[0][rc][jc]),          b0 = unpk(gp[1][rc][jc]);
            float2 a1 = unpk(gp[0][rc][H_ + jc]),     b1 = unpk(gp[1][rc][H_ + jc]);
            float2 a2 = unpk(gp[0][rc][2*H_ + jc]),   b2 = unpk(gp[1][rc][2*H_ + jc]);
            float2 a3 = unpk(gp[0][rc][3*H_ + jc]),   b3 = unpk(gp[1][rc][3*H_ + jc]);
            float ig = sigf((a0.x + a0.y) + (b0.x + b0.y));
            float fg = sigf((a1.x + a1.y) + (b1.x + b1.y));
            float gg = tanh_f((a2.x + a2.y) + (b2.x + b2.y));
            float og = sigf((a3.x + a3.y) + (b3.x + b3.y));
            c_state = fg * c_state + ig * gg;
            float h = og * tanh_f(c_state);
            h_sh[rc][jc] = h;
            if (!FINAL) {
                g_h1[(row0 + rc) * (T_ * H_) + t * H_ + jc] = h;
            }
        }
        __syncthreads();
        buf ^= 1;
    }

    // ---- FC head (layer-2 kernel only) ----
    if (FINAL) {
        for (int r = 0; r < NB; r++) {
            if (tid < FCD) {
                float a = __ldg(&fc1_b[tid]);
                #pragma unroll
                for (int k = 0; k < H_; k++)
                    a += __ldg(&fc1_w[tid * H_ + k]) * h_sh[r][k];
                a = fmaxf(a, 0.0f);
                fcsh[tid] = a * __ldg(&fc2_w[tid]);
            }
            __syncthreads();
            if (tid == 0) {
                float s = __ldg(&fc2_b[0]);
                #pragma unroll
                for (int k = 0; k < FCD; k++) s += fcsh[k];
                out[row0 + r] = s;
            }
            __syncthreads();
        }
    }
}

extern "C" void kernel_launch(void* const* d_in, const int* in_sizes, int n_in,
                              void* d_out, int out_size) {
    const float* x     = (const float*)d_in[0];
    const float* w_ih0 = (const float*)d_in[1];
    const float* w_hh0 = (const float*)d_in[2];
    const float* b_ih0 = (const float*)d_in[3];
    const float* b_hh0 = (const float*)d_in[4];
    const float* w_ih1 = (const float*)d_in[5];
    const float* w_hh1 = (const float*)d_in[6];
    const float* b_ih1 = (const float*)d_in[7];
    const float* b_hh1 = (const float*)d_in[8];
    const float* fc1_w = (const float*)d_in[9];
    const float* fc1_b = (const float*)d_in[10];
    const float* fc2_w = (const float*)d_in[11];
    const float* fc2_b = (const float*)d_in[12];
    float* out = (float*)d_out;

    // Layer 1: reads x, writes g_h1
    lstm_kernel<I_, 20, false><<<B_ / NB, NTH>>>(
        x, w_ih0, w_hh0, b_ih0, b_hh0,
        nullptr, nullptr, nullptr, nullptr, nullptr);

    // Layer 2 + FC head: reads g_h1, writes out
    lstm_kernel<H_, 52, true><<<B_ / NB, NTH>>>(
        nullptr, w_ih1, w_hh1, b_ih1, b_hh1,
        fc1_w, fc1_b, fc2_w, fc2_b, out);
}

// round 3
// speedup vs baseline: 1.3058x; 1.3058x over previous
#include <cuda_runtime.h>

// Problem constants
#define B_   1024
#define T_   512
#define I_   16
#define H_   50
#define G_   200     // 4*H
#define FCD  64
#define NB   7       // batch rows per block -> grid = 148 = one block per SM
#define NTH  224     // 7 warps
#define NCELL (2 * NB * H_)   // 700 cell updates per block per step (both layers)

typedef unsigned long long ull;

// ---- f32x2 packed helpers (sm_103a FFMA2) ----
__device__ __forceinline__ void fma2(ull& acc, ull a, ull b) {
    asm("fma.rn.f32x2 %0, %1, %2, %0;" : "+l"(acc) : "l"(a), "l"(b));
}
__device__ __forceinline__ ull pk2(float x, float y) {
    ull r;
    asm("mov.b64 %0, {%1, %2};" : "=l"(r) : "f"(x), "f"(y));
    return r;
}
__device__ __forceinline__ float2 unpk(ull v) {
    float2 r;
    asm("mov.b64 {%0, %1}, %2;" : "=f"(r.x), "=f"(r.y) : "l"(v));
    return r;
}
__device__ __forceinline__ float sigf(float x) {
    return 1.0f / (1.0f + __expf(-x));
}
__device__ __forceinline__ float tanh_f(float x) {
    return 2.0f / (1.0f + __expf(-2.0f * x)) - 1.0f;
}

// Fused 2-layer LSTM, software-pipelined: iteration `it` computes
//   L1 step it   (uses x_it, h1_{it-1})
//   L2 step it-1 (uses h1_{it-1}, h2_{it-2})
// All gate inputs come from the previous iteration's combine -> one gate
// phase + one combine per iteration. 513 iterations total.
__global__ __launch_bounds__(NTH, 1)
void fused_lstm_kernel(const float* __restrict__ x,
                       const float* __restrict__ w_ih0,  // [G, I]
                       const float* __restrict__ w_hh0,  // [G, H]
                       const float* __restrict__ b_ih0,
                       const float* __restrict__ b_hh0,
                       const float* __restrict__ w_ih1,  // [G, H]
                       const float* __restrict__ w_hh1,  // [G, H]
                       const float* __restrict__ b_ih1,
                       const float* __restrict__ b_hh1,
                       const float* __restrict__ fc1_w,  // [FC, H]
                       const float* __restrict__ fc1_b,
                       const float* __restrict__ fc2_w,  // [1, FC]
                       const float* __restrict__ fc2_b,
                       float* __restrict__ out)          // [B, 1]
{
    __shared__ __align__(16) float x_sh[2][NB][I_];     // double-buffered x tile
    __shared__ __align__(16) float hx[2][NB][52];       // [0]=h1, [1]=h2 (padded)
    __shared__ float gl[2][NB][G_];                     // gate pre-activations per layer

    const int tid  = threadIdx.x;
    const int row0 = blockIdx.x * NB;

    // ---- zero h buffers (pads must be 0) ----
    for (int i = tid; i < 2 * NB * 52; i += NTH) ((float*)hx)[i] = 0.0f;

    // ---- pack weights of BOTH layers into registers ----
    const int g = tid;
    const bool isGate = (g < G_);
    ull wih1p[8];    // L1 x-weights: 16 floats
    ull whh1p[26];   // L1 h-weights: 50 -> 52
    ull wih2p[26];   // L2 input-weights (input = h1): 50 -> 52
    ull whh2p[26];   // L2 h-weights: 50 -> 52
    float bias1 = 0.0f, bias2 = 0.0f;
    if (isGate) {
        #pragma unroll
        for (int k2 = 0; k2 < 8; k2++)
            wih1p[k2] = pk2(__ldg(&w_ih0[g * I_ + 2 * k2]),
                            __ldg(&w_ih0[g * I_ + 2 * k2 + 1]));
        #pragma unroll
        for (int k2 = 0; k2 < 26; k2++) {
            float a0 = (2 * k2     < H_) ? __ldg(&w_hh0[g * H_ + 2 * k2])     : 0.0f;
            float a1 = (2 * k2 + 1 < H_) ? __ldg(&w_hh0[g * H_ + 2 * k2 + 1]) : 0.0f;
            whh1p[k2] = pk2(a0, a1);
            float b0 = (2 * k2     < H_) ? __ldg(&w_ih1[g * H_ + 2 * k2])     : 0.0f;
            float b1 = (2 * k2 + 1 < H_) ? __ldg(&w_ih1[g * H_ + 2 * k2 + 1]) : 0.0f;
            wih2p[k2] = pk2(b0, b1);
            float c0 = (2 * k2     < H_) ? __ldg(&w_hh1[g * H_ + 2 * k2])     : 0.0f;
            float c1 = (2 * k2 + 1 < H_) ? __ldg(&w_hh1[g * H_ + 2 * k2 + 1]) : 0.0f;
            whh2p[k2] = pk2(c0, c1);
        }
        bias1 = __ldg(&b_ih0[g]) + __ldg(&b_hh0[g]);
        bias2 = __ldg(&b_ih1[g]) + __ldg(&b_hh1[g]);
    }

    // ---- combine-phase cell ownership: cells tid, tid+224, tid+448, tid+672 ----
    float c_st[4] = {0.0f, 0.0f, 0.0f, 0.0f};
    int   go[4];          // flat index into gl for this cell's i-gate
    int   ho[4];          // flat index into hx for this cell's h output
    bool  cvalid[4];
    bool  cisl2[4];
    #pragma unroll
    for (int k = 0; k < 4; k++) {
        int cell = tid + k * NTH;
        cvalid[k] = (cell < NCELL);
        int c2 = cvalid[k] ? cell : 0;
        int lay = c2 / (NB * H_);
        int rem = c2 - lay * (NB * H_);
        int r   = rem / H_;
        int j   = rem - r * H_;
        cisl2[k] = (lay == 1);
        go[k] = lay * (NB * G_) + r * G_ + j;
        ho[k] = lay * (NB * 52) + r * 52 + j;
    }

    // ---- preload x_0 ----
    if (tid < NB * I_) {
        int r = tid / I_, kk = tid - r * I_;
        int gr = min(row0 + r, B_ - 1);
        x_sh[0][r][kk] = x[gr * (T_ * I_) + kk];
    }
    __syncthreads();

    int buf = 0;
    for (int it = 0; it <= T_; it++) {
        // -- prefetch x_{it+1} (LDG issued here, hidden under gate math) --
        float pv = 0.0f;
        const bool doPf = (it + 1 < T_) && (tid < NB * I_);
        int pr = 0, pk_ = 0;
        if (doPf) {
            pr = tid / I_; pk_ = tid - pr * I_;
            int gr = min(row0 + pr, B_ - 1);
            pv = x[gr * (T_ * I_) + (it + 1) * I_ + pk_];
        }

        // -- gate phase: both layers' pre-activations --
        if (isGate) {
            ull a1[NB], a2[NB];
            #pragma unroll
            for (int r = 0; r < NB; r++) {
                a1[r] = pk2(bias1, 0.0f);
                a2[r] = pk2(bias2, 0.0f);
            }
            // L1 x part (4 quad-chunks)
            #pragma unroll
            for (int q = 0; q < 4; q++) {
                #pragma unroll
                for (int r = 0; r < NB; r++) {
                    const ulonglong2 v = *(const ulonglong2*)&x_sh[buf][r][4 * q];
                    fma2(a1[r], wih1p[2 * q],     v.x);
                    fma2(a1[r], wih1p[2 * q + 1], v.y);
                }
            }
            // h1 part: feeds BOTH a1 (L1 recurrent) and a2 (L2 input) -> 1 LDS : 4 FFMA2
            #pragma unroll
            for (int q = 0; q < 13; q++) {
                #pragma unroll
                for (int r = 0; r < NB; r++) {
                    const ulonglong2 v = *(const ulonglong2*)&hx[0][r][4 * q];
                    fma2(a1[r], whh1p[2 * q],     v.x);
                    fma2(a1[r], whh1p[2 * q + 1], v.y);
                    fma2(a2[r], wih2p[2 * q],     v.x);
                    fma2(a2[r], wih2p[2 * q + 1], v.y);
                }
            }
            // h2 part (L2 recurrent)
            #pragma unroll
            for (int q = 0; q < 13; q++) {
                #pragma unroll
                for (int r = 0; r < NB; r++) {
                    const ulonglong2 v = *(const ulonglong2*)&hx[1][r][4 * q];
                    fma2(a2[r], whh2p[2 * q],     v.x);
                    fma2(a2[r], whh2p[2 * q + 1], v.y);
                }
            }
            #pragma unroll
            for (int r = 0; r < NB; r++) {
                float2 s1 = unpk(a1[r]);
                gl[0][r][g] = s1.x + s1.y;
                float2 s2 = unpk(a2[r]);
                gl[1][r][g] = s2.x + s2.y;
            }
        }
        __syncthreads();

        // -- combine: up to 4 cells per thread (gate order i, f, g, o) --
        #pragma unroll
        for (int k = 0; k < 4; k++) {
            if (cvalid[k]) {
                const bool act = cisl2[k] ? (it >= 1) : (it < T_);
                if (act) {
                    const float* p = &((const float*)gl)[go[k]];
                    float ig = sigf(p[0]);
                    float fg = sigf(p[H_]);
                    float gg = tanh_f(p[2 * H_]);
                    float og = sigf(p[3 * H_]);
                    c_st[k] = fg * c_st[k] + ig * gg;
                    ((float*)hx)[ho[k]] = og * tanh_f(c_st[k]);
                }
            }
        }
        // commit prefetched x into the other buffer
        if (doPf) x_sh[buf ^ 1][pr][pk_] = pv;
        __syncthreads();
        buf ^= 1;
    }

    // ---- FC head: one warp per batch row, shfl reduction, no barriers ----
    const int wid  = tid / 32;
    const int lane = tid - wid * 32;
    const int row  = row0 + wid;
    if (row < B_) {
        float s = 0.0f;
        #pragma unroll
        for (int uu = 0; uu < 2; uu++) {
            const int u = lane + uu * 32;
            float a = __ldg(&fc1_b[u]);
            #pragma unroll
            for (int k = 0; k < H_; k++)
                a += __ldg(&fc1_w[u * H_ + k]) * hx[1][wid][k];
            a = fmaxf(a, 0.0f);
            s += a * __ldg(&fc2_w[u]);
        }
        #pragma unroll
        for (int off = 16; off > 0; off >>= 1)
            s += __shfl_down_sync(0xffffffffu, s, off);
        if (lane == 0) out[row] = s + __ldg(&fc2_b[0]);
    }
}

extern "C" void kernel_launch(void* const* d_in, const int* in_sizes, int n_in,
                              void* d_out, int out_size) {
    const float* x     = (const float*)d_in[0];
    const float* w_ih0 = (const float*)d_in[1];
    const float* w_hh0 = (const float*)d_in[2];
    const float* b_ih0 = (const float*)d_in[3];
    const float* b_hh0 = (const float*)d_in[4];
    const float* w_ih1 = (const float*)d_in[5];
    const float* w_hh1 = (const float*)d_in[6];
    const float* b_ih1 = (const float*)d_in[7];
    const float* b_hh1 = (const float*)d_in[8];
    const float* fc1_w = (const float*)d_in[9];
    const float* fc1_b = (const float*)d_in[10];
    const float* fc2_w = (const float*)d_in[11];
    const float* fc2_b = (const float*)d_in[12];
    float* out = (float*)d_out;

    const int grid = (B_ + NB - 1) / NB;   // 147 -> need ceil: 1024/7 = 146.28 -> 147
    fused_lstm_kernel<<<grid, NTH>>>(
        x, w_ih0, w_hh0, b_ih0, b_hh0,
        w_ih1, w_hh1, b_ih1, b_hh1,
        fc1_w, fc1_b, fc2_w, fc2_b, out);
}